// round 15
// baseline (speedup 1.0000x reference)
#include <cuda_runtime.h>
#include <cuda_bf16.h>
#include <cstdint>

// Problem constants
#define B_   64
#define N_   100
#define D_   2048
#define NR_  16
#define DK_  64
#define DV_  128
#define P_   (B_*N_)          // 6400
#define KQ_COLS (NR_*DK_)     // 1024
#define PAIRS (B_*N_*N_)      // 640000

// ---------------------------------------------------------------------------
// Scratch (device globals; allocation APIs are forbidden)
// ---------------------------------------------------------------------------
__device__ float g_K[P_ * KQ_COLS];          // 6400 x 1024
__device__ float g_Q[P_ * KQ_COLS];          // 6400 x 1024
__device__ float g_gwT[B_ * NR_ * N_ * N_];  // [b][h][i*100+j]; e overwrites gw

__device__ __align__(16) __nv_bfloat16 g_Ahi[P_ * D_];        // [m][k]
__device__ __align__(16) __nv_bfloat16 g_Alo[P_ * D_];
__device__ __align__(16) __nv_bfloat16 g_WKhi[D_ * KQ_COLS];  // [k][n]
__device__ __align__(16) __nv_bfloat16 g_WKlo[D_ * KQ_COLS];
__device__ __align__(16) __nv_bfloat16 g_WQhi[D_ * KQ_COLS];
__device__ __align__(16) __nv_bfloat16 g_WQlo[D_ * KQ_COLS];

// ---------------------------------------------------------------------------
// PTX helpers
// ---------------------------------------------------------------------------
__device__ __forceinline__ uint32_t smem_u32(const void* p) {
    uint32_t a;
    asm("{ .reg .u64 t; cvta.to.shared.u64 t, %1; cvt.u32.u64 %0, t; }"
        : "=r"(a) : "l"(p));
    return a;
}
__device__ __forceinline__ void cp_async16(uint32_t dst, const void* src) {
    asm volatile("cp.async.cg.shared.global [%0], [%1], 16;" :: "r"(dst), "l"(src));
}
#define CP_COMMIT() asm volatile("cp.async.commit_group;" ::: "memory")
#define CP_WAIT(n)  asm volatile("cp.async.wait_group %0;" :: "n"(n) : "memory")

// Bulk async copy (TMA engine; plain non-tensor variant, sm_90 baseline PTX)
__device__ __forceinline__ void cp_bulk(uint32_t dst, const void* src,
                                        uint32_t bytes, uint32_t mbar) {
    asm volatile(
        "cp.async.bulk.shared::cta.global.mbarrier::complete_tx::bytes "
        "[%0], [%1], %2, [%3];"
        :: "r"(dst), "l"(src), "r"(bytes), "r"(mbar) : "memory");
}
#define MBARRIER_INIT(addr, cnt) \
    asm volatile("mbarrier.init.shared.b64 [%0], %1;" :: "r"(addr), "r"(cnt) : "memory")
#define MBARRIER_EXPECT_TX(addr, bytes) \
    asm volatile("mbarrier.arrive.expect_tx.shared.b64 _, [%0], %1;" \
                 :: "r"(addr), "r"(bytes) : "memory")
#define MBARRIER_WAIT_PARITY(addr, par) do {                                      \
    uint32_t _m = (addr), _p = (par), _d;                                         \
    asm volatile("{\n\t.reg .pred p;\n\t"                                         \
        "mbarrier.try_wait.parity.acquire.cta.shared::cta.b64 p, [%1], %2;\n\t"   \
        "selp.b32 %0, 1, 0, p;\n\t}" : "=r"(_d) : "r"(_m), "r"(_p) : "memory");   \
    if (!_d) {                                                                    \
        asm volatile("{\n\t.reg .pred P1;\n\t"                                    \
        "WL_%=:\n\t"                                                              \
        "mbarrier.try_wait.parity.acquire.cta.shared::cta.b64 P1, [%0], %1, 0x989680;\n\t" \
        "@P1 bra.uni WD_%=;\n\t"                                                  \
        "bra.uni WL_%=;\n\t"                                                      \
        "WD_%=:\n\t}" :: "r"(_m), "r"(_p) : "memory");                            \
    }                                                                             \
} while (0)

__device__ __forceinline__ void ldsm_x4(uint32_t addr, uint32_t* f) {
    asm volatile("ldmatrix.sync.aligned.m8n8.x4.shared.b16 {%0,%1,%2,%3}, [%4];"
                 : "=r"(f[0]), "=r"(f[1]), "=r"(f[2]), "=r"(f[3]) : "r"(addr));
}
__device__ __forceinline__ void ldsm_x4t(uint32_t addr, uint32_t* f) {
    asm volatile("ldmatrix.sync.aligned.m8n8.x4.trans.shared.b16 {%0,%1,%2,%3}, [%4];"
                 : "=r"(f[0]), "=r"(f[1]), "=r"(f[2]), "=r"(f[3]) : "r"(addr));
}
__device__ __forceinline__ void mma_bf16(float* d, const uint32_t* a, const uint32_t* b) {
    asm volatile("mma.sync.aligned.m16n8k16.row.col.f32.bf16.bf16.f32 "
                 "{%0,%1,%2,%3}, {%4,%5,%6,%7}, {%8,%9}, {%0,%1,%2,%3};"
                 : "+f"(d[0]), "+f"(d[1]), "+f"(d[2]), "+f"(d[3])
                 : "r"(a[0]), "r"(a[1]), "r"(a[2]), "r"(a[3]),
                   "r"(b[0]), "r"(b[1]));
}

// ---------------------------------------------------------------------------
// Kernel 1: fused gate + conversions (unchanged).
// ---------------------------------------------------------------------------
#define GATE_BLKS 1250
#define CONVA_BLKS 12800
#define CONVW_BLKS 2048
#define PRE_BLKS (GATE_BLKS + CONVA_BLKS + 2 * CONVW_BLKS)

__global__ __launch_bounds__(256, 4) void pre_kernel(
    const float* __restrict__ G, const float* __restrict__ Wg,
    const float* __restrict__ bg, float* __restrict__ gwout,
    const float* __restrict__ A, const float* __restrict__ WK,
    const float* __restrict__ WQ,
    __nv_bfloat16* __restrict__ Ah, __nv_bfloat16* __restrict__ Al,
    __nv_bfloat16* __restrict__ WKh, __nv_bfloat16* __restrict__ WKl,
    __nv_bfloat16* __restrict__ WQh, __nv_bfloat16* __restrict__ WQl)
{
    int bx = blockIdx.x;
    int tid = threadIdx.x;

    if (bx >= GATE_BLKS) {
        int cb = bx - GATE_BLKS;
        const float* X;
        __nv_bfloat16 *hi, *lo;
        int seg;
        if (cb < CONVA_BLKS)                  { X = A;  hi = Ah;  lo = Al;  seg = cb; }
        else if (cb < CONVA_BLKS + CONVW_BLKS){ X = WK; hi = WKh; lo = WKl; seg = cb - CONVA_BLKS; }
        else                                  { X = WQ; hi = WQh; lo = WQl; seg = cb - CONVA_BLKS - CONVW_BLKS; }

        size_t i = ((size_t)seg * 256 + tid) * 4;
        float4 v = *(const float4*)(X + i);
        float xs[4] = {v.x, v.y, v.z, v.w};
        __nv_bfloat16 h[4], l[4];
#pragma unroll
        for (int e = 0; e < 4; e++) {
            h[e] = __float2bfloat16(xs[e]);
            l[e] = __float2bfloat16(xs[e] - __bfloat162float(h[e]));
        }
        *(__nv_bfloat162*)(hi + i)     = __nv_bfloat162(h[0], h[1]);
        *(__nv_bfloat162*)(hi + i + 2) = __nv_bfloat162(h[2], h[3]);
        *(__nv_bfloat162*)(lo + i)     = __nv_bfloat162(l[0], l[1]);
        *(__nv_bfloat162*)(lo + i + 2) = __nv_bfloat162(l[2], l[3]);
        return;
    }

    __shared__ float sW[64][16];
    __shared__ float sb[16];
    if (tid < 16) sb[tid] = bg[tid];
    for (int idx = tid; idx < 64 * 16; idx += 256)
        sW[idx >> 4][idx & 15] = Wg[idx];
    __syncthreads();

    int p0 = bx * 512 + tid;

    float acc0[16], acc1[16];
#pragma unroll
    for (int hh = 0; hh < 16; hh++) { acc0[hh] = sb[hh]; acc1[hh] = sb[hh]; }

    const float4* g4 = (const float4*)(G + (size_t)p0 * 64);

#pragma unroll 4
    for (int k4 = 0; k4 < 16; k4++) {
        float4 gv0 = g4[k4];
        float4 gv1 = g4[256 * 16 + k4];
        float a0[4] = {gv0.x, gv0.y, gv0.z, gv0.w};
        float a1[4] = {gv1.x, gv1.y, gv1.z, gv1.w};
#pragma unroll
        for (int e = 0; e < 4; e++) {
            int k = 4 * k4 + e;
            float ge0 = a0[e], ge1 = a1[e];
            float4 w0 = *(const float4*)&sW[k][0];
            acc0[0] += ge0 * w0.x; acc1[0] += ge1 * w0.x;
            acc0[1] += ge0 * w0.y; acc1[1] += ge1 * w0.y;
            acc0[2] += ge0 * w0.z; acc1[2] += ge1 * w0.z;
            acc0[3] += ge0 * w0.w; acc1[3] += ge1 * w0.w;
            float4 w1 = *(const float4*)&sW[k][4];
            acc0[4] += ge0 * w1.x; acc1[4] += ge1 * w1.x;
            acc0[5] += ge0 * w1.y; acc1[5] += ge1 * w1.y;
            acc0[6] += ge0 * w1.z; acc1[6] += ge1 * w1.z;
            acc0[7] += ge0 * w1.w; acc1[7] += ge1 * w1.w;
            float4 w2 = *(const float4*)&sW[k][8];
            acc0[8]  += ge0 * w2.x; acc1[8]  += ge1 * w2.x;
            acc0[9]  += ge0 * w2.y; acc1[9]  += ge1 * w2.y;
            acc0[10] += ge0 * w2.z; acc1[10] += ge1 * w2.z;
            acc0[11] += ge0 * w2.w; acc1[11] += ge1 * w2.w;
            float4 w3 = *(const float4*)&sW[k][12];
            acc0[12] += ge0 * w3.x; acc1[12] += ge1 * w3.x;
            acc0[13] += ge0 * w3.y; acc1[13] += ge1 * w3.y;
            acc0[14] += ge0 * w3.z; acc1[14] += ge1 * w3.z;
            acc0[15] += ge0 * w3.w; acc1[15] += ge1 * w3.w;
        }
    }

#pragma unroll
    for (int q = 0; q < 2; q++) {
        int p  = p0 + q * 256;
        int b  = p / (N_ * N_);
        int lp = p - b * (N_ * N_);
        float* ob = gwout + (size_t)b * (NR_ * N_ * N_) + lp;
        float* ac = q ? acc1 : acc0;
#pragma unroll
        for (int hh = 0; hh < 16; hh++)
            ob[(size_t)hh * (N_ * N_)] = fmaxf(ac[hh], 1e-6f);
    }
}

// ---------------------------------------------------------------------------
// Kernel 2: bf16 3-pass GEMM, cp.async.bulk loads (TMA engine, no LDGSTS).
// CTA tile 256x128, 8 warps (4x2), warp tile 64x64, KC=32, 3-stage mbarrier
// pipeline.  Padded un-swizzled smem rows (A 80B, W 272B) -> conflict-free
// ldmatrix.  grid (8, 25, 2): z=0->K, z=1->Q.
//
// stage layout: Ahi @0 (256 rows x 80B = 20480), Alo @20480,
//               Whi @40960 (32 rows x 272B = 8704), Wlo @49664.  stage 58368.
// ---------------------------------------------------------------------------
#define KC 32
#define NCHUNKS (D_ / KC)        // 64
#define A_ROWB 80
#define W_ROWB 272
#define ST_ALO 20480
#define ST_WHI 40960
#define ST_WLO 49664
#define STAGEBYTES 58368
#define NSTAGES 3
#define GEMM_SMEM (NSTAGES * STAGEBYTES)
#define CHUNK_TX 49152u          // 2*256*64 + 2*32*256 bytes per chunk

__global__ __launch_bounds__(256, 1) void gemm_mma(
    const __nv_bfloat16* __restrict__ Ah, const __nv_bfloat16* __restrict__ Al,
    const __nv_bfloat16* __restrict__ WKh, const __nv_bfloat16* __restrict__ WKl,
    const __nv_bfloat16* __restrict__ WQh, const __nv_bfloat16* __restrict__ WQl,
    const float* __restrict__ bK, const float* __restrict__ bQ,
    float* __restrict__ gK, float* __restrict__ gQ)
{
    extern __shared__ char smem[];
    __shared__ __align__(8) uint64_t mbar_s[NSTAGES];
    uint32_t sbase = smem_u32(smem);
    uint32_t mb[NSTAGES];
#pragma unroll
    for (int s = 0; s < NSTAGES; s++) mb[s] = smem_u32(&mbar_s[s]);

    int tid = threadIdx.x;
    int wid = tid >> 5, lane = tid & 31;
    int wm = wid >> 1, wn = wid & 1;   // 4 x 2 warp grid, warp tile 64x64

    const __nv_bfloat16 *Wh, *Wl;
    const float* bias;
    float* C;
    if (blockIdx.z == 0) { Wh = WKh; Wl = WKl; bias = bK; C = gK; }
    else                 { Wh = WQh; Wl = WQl; bias = bQ; C = gQ; }

    int m0 = blockIdx.y * 256;
    int n0 = blockIdx.x * 128;

    if (tid == 0) {
#pragma unroll
        for (int s = 0; s < NSTAGES; s++) MBARRIER_INIT(mb[s], 1);
    }
    __syncthreads();

    float acc[4][8][4];
#pragma unroll
    for (int mi = 0; mi < 4; mi++)
#pragma unroll
        for (int nj = 0; nj < 8; nj++)
#pragma unroll
            for (int e = 0; e < 4; e++) acc[mi][nj][e] = 0.f;

    // ---- bulk-load one K-chunk into stage s ----
    auto load_chunk = [&](int c, int s) {
        int k0 = c * KC;
        uint32_t base = sbase + s * STAGEBYTES;
        if (tid == 0) MBARRIER_EXPECT_TX(mb[s], CHUNK_TX);
        // A hi/lo: one 64B row per thread each
        {
            int r = tid;   // 0..255
            const __nv_bfloat16* s1 = Ah + (size_t)(m0 + r) * 2048 + k0;
            const __nv_bfloat16* s2 = Al + (size_t)(m0 + r) * 2048 + k0;
            cp_bulk(base + r * A_ROWB, s1, 64, mb[s]);
            cp_bulk(base + ST_ALO + r * A_ROWB, s2, 64, mb[s]);
        }
        // W hi: threads 0..31, W lo: threads 32..63 (one 256B row each)
        if (tid < 32) {
            int k = tid;
            cp_bulk(base + ST_WHI + k * W_ROWB,
                    Wh + (size_t)(k0 + k) * 1024 + n0, 256, mb[s]);
        } else if (tid < 64) {
            int k = tid - 32;
            cp_bulk(base + ST_WLO + k * W_ROWB,
                    Wl + (size_t)(k0 + k) * 1024 + n0, 256, mb[s]);
        }
    };

    load_chunk(0, 0);
    load_chunk(1, 1);
    load_chunk(2, 2);

    // ldmatrix lane address components (same mapping as the R8 winner)
    int ar  = lane & 15;          // A: row within 16-row block
    int acs = lane >> 4;          // A: 16B k-chunk half select
    int wg8 = lane >> 3;          // W: 8-lane group 0..3
    int wk8 = lane & 7;
    int wks = (wg8 & 1) * 8;
    int wns = wg8 >> 1;

    int s = 0;
    for (int c = 0; c < NCHUNKS; c++) {
        MBARRIER_WAIT_PARITY(mb[s], (uint32_t)((c / NSTAGES) & 1));
        uint32_t base = sbase + s * STAGEBYTES;

#pragma unroll
        for (int ki = 0; ki < 2; ki++) {
            uint32_t afh[4][4], afl[4][4];
#pragma unroll
            for (int mi = 0; mi < 4; mi++) {
                int r = wm * 64 + mi * 16 + ar;
                int cc = 2 * ki + acs;             // 0..3
                uint32_t off = (uint32_t)(r * A_ROWB + cc * 16);
                ldsm_x4(base + off, afh[mi]);
                ldsm_x4(base + ST_ALO + off, afl[mi]);
            }
#pragma unroll
            for (int np = 0; np < 4; np++) {
                int k  = ki * 16 + wks + wk8;      // 0..31
                int cc = wn * 8 + 2 * np + wns;    // 0..15
                uint32_t off = (uint32_t)(k * W_ROWB + cc * 16);
                uint32_t qh[4], ql[4];
                ldsm_x4t(base + ST_WHI + off, qh);
                ldsm_x4t(base + ST_WLO + off, ql);
                uint32_t bh0[2] = {qh[0], qh[1]}, bh1[2] = {qh[2], qh[3]};
                uint32_t bl0[2] = {ql[0], ql[1]}, bl1[2] = {ql[2], ql[3]};
#pragma unroll
                for (int mi = 0; mi < 4; mi++) {
                    mma_bf16(acc[mi][2 * np],     afh[mi], bh0);
                    mma_bf16(acc[mi][2 * np],     afh[mi], bl0);
                    mma_bf16(acc[mi][2 * np],     afl[mi], bh0);
                    mma_bf16(acc[mi][2 * np + 1], afh[mi], bh1);
                    mma_bf16(acc[mi][2 * np + 1], afh[mi], bl1);
                    mma_bf16(acc[mi][2 * np + 1], afl[mi], bh1);
                }
            }
        }
        __syncthreads();                    // all warps done with stage s
        if (c + NSTAGES < NCHUNKS) load_chunk(c + NSTAGES, s);
        s = (s == NSTAGES - 1) ? 0 : s + 1;
    }

    // ---- epilogue: add bias, store fp32 ----
    int g = lane >> 2, t4 = lane & 3;
    float bcol[8][2];
#pragma unroll
    for (int nj = 0; nj < 8; nj++) {
        int col = n0 + wn * 64 + nj * 8 + t4 * 2;
        bcol[nj][0] = __ldg(bias + col);
        bcol[nj][1] = __ldg(bias + col + 1);
    }
#pragma unroll
    for (int mi = 0; mi < 4; mi++) {
#pragma unroll
        for (int half = 0; half < 2; half++) {
            int m = m0 + wm * 64 + mi * 16 + g + half * 8;
            float* crow = C + (size_t)m * 1024 + n0 + wn * 64;
#pragma unroll
            for (int nj = 0; nj < 8; nj++) {
                int col = nj * 8 + t4 * 2;
                float2 v;
                v.x = acc[mi][nj][half * 2 + 0] + bcol[nj][0];
                v.y = acc[mi][nj][half * 2 + 1] + bcol[nj][1];
                *(float2*)(crow + col) = v;
            }
        }
    }
}

// ---------------------------------------------------------------------------
// Kernel 3: attention logits per (b,h), in-place e over g_gwT (unchanged).
// ---------------------------------------------------------------------------
#define KQPAD 65

__global__ __launch_bounds__(256, 3) void attn_logits_kernel(
    const float* __restrict__ Kmat, const float* __restrict__ Qmat,
    float* __restrict__ gw)
{
    extern __shared__ float sm[];
    float* Ks = sm;
    float* Qs = sm + 112 * KQPAD;

    int h = blockIdx.x;
    int b = blockIdx.y;
    int tid = threadIdx.x;
    int tx = tid & 15, ty = tid >> 4;

    for (int idx = tid; idx < 112 * 64; idx += 256) {
        int i = idx >> 6, d = idx & 63;
        float kv = 0.f, qv = 0.f;
        if (i < 100) {
            size_t gofs = (size_t)(b * 100 + i) * 1024 + h * 64 + d;
            kv = Kmat[gofs];
            qv = Qmat[gofs];
        }
        Ks[i * KQPAD + d] = kv;
        Qs[i * KQPAD + d] = qv;
    }
    __syncthreads();

    float acc[7][7];
#pragma unroll
    for (int ii = 0; ii < 7; ii++)
#pragma unroll
        for (int jj = 0; jj < 7; jj++) acc[ii][jj] = 0.f;

    for (int d = 0; d < 64; d++) {
        float kk[7], qq[7];
#pragma unroll
        for (int ii = 0; ii < 7; ii++) kk[ii] = Ks[(ty + 16 * ii) * KQPAD + d];
#pragma unroll
        for (int jj = 0; jj < 7; jj++) qq[jj] = Qs[(tx + 16 * jj) * KQPAD + d];
#pragma unroll
        for (int ii = 0; ii < 7; ii++)
#pragma unroll
            for (int jj = 0; jj < 7; jj++)
                acc[ii][jj] += kk[ii] * qq[jj];
    }

    float* gwb = gw + ((size_t)(b * 16 + h)) * 10000;
#pragma unroll
    for (int ii = 0; ii < 7; ii++) {
        int i = ty + 16 * ii;
        if (i >= 100) continue;
#pragma unroll
        for (int jj = 0; jj < 7; jj++) {
            int j = tx + 16 * jj;
            if (j >= 100) continue;
            float* ep = gwb + i * 100 + j;
            *ep = *ep * __expf(acc[ii][jj] * 0.125f);
        }
    }
}

// ---------------------------------------------------------------------------
// Kernel 4: AV per (b,h) (unchanged).
// ---------------------------------------------------------------------------
#define AVPAD 112
#define AV_FIN0 12800
#define AV_CS   (AV_FIN0 + 2 * 25 * AVPAD)
#define AV_SMEM ((AV_CS + 112) * 4)

__global__ __launch_bounds__(256, 3) void attn_av_kernel(
    const float* __restrict__ e_g, const float* __restrict__ A,
    const float* __restrict__ wsp, const float* __restrict__ bsp,
    float* __restrict__ out)
{
    extern __shared__ float sm[];
    uint32_t sbase = smem_u32(sm);

    int h = blockIdx.x;
    int b = blockIdx.y;
    int tid = threadIdx.x;
    int tx = tid & 15, ty = tid >> 4;

    const float* eb = e_g + ((size_t)(b * 16 + h)) * 10000;

    for (int idx = tid; idx < 3200; idx += 256) {
        int i = idx >> 5, cc = idx & 31;
        cp_async16(sbase + (uint32_t)(i * 512 + cc * 16),
                   A + (size_t)(b * 100 + i) * 2048 + h * 128 + cc * 4);
    }
    auto load_echunk = [&](int c) {
        uint32_t dst0 = sbase + (uint32_t)((AV_FIN0 + (c & 1) * 25 * AVPAD) * 4);
        for (int idx = tid; idx < 625; idx += 256) {
            int r = idx / 25, cc = idx - r * 25;
            cp_async16(dst0 + (uint32_t)(r * AVPAD * 4 + cc * 16),
                       eb + (25 * c + r) * 100 + cc * 4);
        }
        CP_COMMIT();
    };
    load_echunk(0);
    load_echunk(1);

    float r[7][8];
#pragma unroll
    for (int jj = 0; jj < 7; jj++)
#pragma unroll
        for (int dd = 0; dd < 8; dd++) r[jj][dd] = 0.f;
    float cacc = 0.f;

    for (int c = 0; c < 4; c++) {
        if (c < 3) { CP_WAIT(1); } else { CP_WAIT(0); }
        __syncthreads();
        const float* fb = sm + AV_FIN0 + (c & 1) * 25 * AVPAD;

        if (tid < 100) {
#pragma unroll 5
            for (int ii = 0; ii < 25; ii++) cacc += fb[ii * AVPAD + tid];
        }

        for (int ii = 0; ii < 25; ii++) {
            int i = 25 * c + ii;
            float vv[8], ff[7];
#pragma unroll
            for (int dd = 0; dd < 8; dd++) vv[dd] = sm[i * 128 + tx + 16 * dd];
#pragma unroll
            for (int jj = 0; jj < 7; jj++) ff[jj] = fb[ii * AVPAD + ty + 16 * jj];
#pragma unroll
            for (int jj = 0; jj < 7; jj++)
#pragma unroll
                for (int dd = 0; dd < 8; dd++)
                    r[jj][dd] += vv[dd] * ff[jj];
        }
        __syncthreads();
        if (c + 2 < 4) load_echunk(c + 2);
    }

    if (tid < 100) sm[AV_CS + tid] = cacc;
    __syncthreads();

    float ws = wsp[0], bs = bsp[0];
#pragma unroll
    for (int jj = 0; jj < 7; jj++) {
        int j = ty + 16 * jj;
        if (j >= 100) continue;
        float rc = (1.f / sm[AV_CS + j]) * ws;
        float* orow = out + (size_t)(b * 100 + j) * 2048 + h * 128;
#pragma unroll
        for (int dd = 0; dd < 8; dd++) {
            int d = tx + 16 * dd;
            orow[d] = (r[jj][dd] * rc) + bs;
        }
    }
}

// ---------------------------------------------------------------------------
// Launcher
// ---------------------------------------------------------------------------
extern "C" void kernel_launch(void* const* d_in, const int* in_sizes, int n_in,
                              void* d_out, int out_size)
{
    const float* a_feat = (const float*)d_in[0];
    const float* g_feat = (const float*)d_in[1];
    const float* W_g    = (const float*)d_in[4];
    const float* b_g    = (const float*)d_in[5];
    const float* W_K    = (const float*)d_in[6];
    const float* b_K    = (const float*)d_in[7];
    const float* W_Q    = (const float*)d_in[8];
    const float* b_Q    = (const float*)d_in[9];
    const float* w_s    = (const float*)d_in[10];
    const float* b_s    = (const float*)d_in[11];
    float* out          = (float*)d_out;

    float *Kp, *Qp, *gwp;
    __nv_bfloat16 *Ahp, *Alp, *WKhp, *WKlp, *WQhp, *WQlp;
    cudaGetSymbolAddress((void**)&Kp,  g_K);
    cudaGetSymbolAddress((void**)&Qp,  g_Q);
    cudaGetSymbolAddress((void**)&gwp, g_gwT);
    cudaGetSymbolAddress((void**)&Ahp, g_Ahi);
    cudaGetSymbolAddress((void**)&Alp, g_Alo);
    cudaGetSymbolAddress((void**)&WKhp, g_WKhi);
    cudaGetSymbolAddress((void**)&WKlp, g_WKlo);
    cudaGetSymbolAddress((void**)&WQhp, g_WQhi);
    cudaGetSymbolAddress((void**)&WQlp, g_WQlo);

    // 1) fused gate + conversions
    pre_kernel<<<PRE_BLKS, 256>>>(g_feat, W_g, b_g, gwp,
                                  a_feat, W_K, W_Q,
                                  Ahp, Alp, WKhp, WKlp, WQhp, WQlp);

    // 2) K & Q GEMMs (256x128 CTA, 64x64 warp tile, KC=32, bulk-copy pipeline)
    cudaFuncSetAttribute(gemm_mma, cudaFuncAttributeMaxDynamicSharedMemorySize,
                         GEMM_SMEM);
    dim3 ggrid(KQ_COLS / 128, P_ / 256, 2);   // (8, 25, 2)
    gemm_mma<<<ggrid, 256, GEMM_SMEM>>>(Ahp, Alp, WKhp, WKlp, WQhp, WQlp,
                                        b_K, b_Q, Kp, Qp);

    // 3) logits (e overwrites gw in place)
    int lsmem = 2 * 112 * KQPAD * (int)sizeof(float);
    cudaFuncSetAttribute(attn_logits_kernel,
                         cudaFuncAttributeMaxDynamicSharedMemorySize, lsmem);
    dim3 agrid(NR_, B_);
    attn_logits_kernel<<<agrid, 256, lsmem>>>(Kp, Qp, gwp);

    // 4) AV + normalize + affine
    cudaFuncSetAttribute(attn_av_kernel,
                         cudaFuncAttributeMaxDynamicSharedMemorySize, AV_SMEM);
    attn_av_kernel<<<agrid, 256, AV_SMEM>>>(gwp, a_feat, w_s, b_s, out);
}